// round 5
// baseline (speedup 1.0000x reference)
#include <cuda_runtime.h>
#include <math.h>

#define NN 4
#define CC 512
#define DD 768
#define HH 12
#define EE 20
#define MMENT 4
#define PP 380
#define NP 1520
#define LL 97
#define DIM2 1536
#define DIM3 2304
#define DIM4 3072
#define NEGV (-1e30f)

// ---------------- static device scratch ----------------
__device__ float g_eemb[NN*EE*MMENT*DD];
__device__ float g_eatt[NN*EE*MMENT*CC];
__device__ float g_glob[NN*EE*DD];
__device__ float g_A[NN*EE*DD];
__device__ float g_B[NN*EE*DD];
__device__ float g_edge[NN*EE*EE*DD];
__device__ float g_q[NP*DIM2];
__device__ float g_pa[NP*CC];
__device__ float g_hcat[NP*DIM3];
__device__ float g_tcat[NP*DIM3];
__device__ float g_qW[NP*DIM4];
__device__ float g_pathraw[NP*DIM4];
__device__ float g_hs[NP*DD];
__device__ float g_ts[NP*DD];
__device__ float g_part[4*NP*DD];   // split-K partials / bil partials

// ---------------- K1: gather e_emb, head-mean e_att, logsumexp glob ----------------
__global__ void k_gather(const float* __restrict__ seq, const float* __restrict__ att,
                         const int* __restrict__ ms)
{
    int ne = blockIdx.x;
    int n  = ne / EE;
    int tid = threadIdx.x;
    for (int m = 0; m < MMENT; m++) {
        int pos = ms[ne*MMENT + m] + 1;
        const float* srow = seq + ((size_t)n*CC + pos)*DD;
        float* erow = g_eemb + ((size_t)ne*MMENT + m)*DD;
        for (int d = tid; d < DD; d += blockDim.x) erow[d] = srow[d];
        float* arow = g_eatt + ((size_t)ne*MMENT + m)*CC;
        for (int c = tid; c < CC; c += blockDim.x) {
            float s = 0.f;
            #pragma unroll
            for (int h = 0; h < HH; h++)
                s += att[(((size_t)n*HH + h)*CC + pos)*CC + c];
            arow[c] = s * (1.0f/HH);
        }
    }
    __syncthreads();
    for (int d = tid; d < DD; d += blockDim.x) {
        float x0 = g_eemb[((size_t)ne*MMENT+0)*DD+d];
        float x1 = g_eemb[((size_t)ne*MMENT+1)*DD+d];
        float x2 = g_eemb[((size_t)ne*MMENT+2)*DD+d];
        float x3 = g_eemb[((size_t)ne*MMENT+3)*DD+d];
        float mx = fmaxf(fmaxf(x0,x1), fmaxf(x2,x3));
        float s = expf(x0-mx)+expf(x1-mx)+expf(x2-mx)+expf(x3-mx);
        g_glob[(size_t)ne*DD + d] = mx + logf(s);
    }
}

// ---------------- K3: edge = relu(A[u] + B[v] + bm) ----------------
__global__ void k_edge(const float* __restrict__ bm)
{
    int idx = blockIdx.x*blockDim.x + threadIdx.x;
    const int total = NN*EE*EE*DD;
    if (idx >= total) return;
    int d = idx % DD;
    int v = (idx / DD) % EE;
    int u = (idx / (DD*EE)) % EE;
    int n = idx / (DD*EE*EE);
    float val = g_A[((size_t)n*EE+u)*DD+d] + g_B[((size_t)n*EE+v)*DD+d] + bm[d];
    g_edge[idx] = fmaxf(val, 0.f);
}

// ---------------- K4: pair attention, new_hs/new_ts, pa ----------------
__global__ void k_pair(const int* __restrict__ hts, const int* __restrict__ ms)
{
    int r = blockIdx.x;
    int n = r / PP;
    int h = hts[r*2 + 0];
    int t = hts[r*2 + 1];
    __shared__ int   s_ph[MMENT], s_pt[MMENT];
    __shared__ float s_phatt[MMENT], s_ptatt[MMENT];
    __shared__ float s_red[256];
    int tid = threadIdx.x;
    if (tid < MMENT) {
        s_ph[tid] = ms[((size_t)n*EE+h)*MMENT + tid] + 1;
        s_pt[tid] = ms[((size_t)n*EE+t)*MMENT + tid] + 1;
    }
    __syncthreads();
    if (tid < 2*MMENT) {
        int m2 = tid & (MMENT-1);
        float s = 0.f;
        if (tid < MMENT) {
            for (int m1 = 0; m1 < MMENT; m1++)
                s += g_eatt[((size_t)(n*EE+h)*MMENT+m1)*CC + s_pt[m2]];
            s_phatt[m2] = s * (1.f/MMENT);
        } else {
            for (int m1 = 0; m1 < MMENT; m1++)
                s += g_eatt[((size_t)(n*EE+t)*MMENT+m1)*CC + s_ph[m2]];
            s_ptatt[m2] = s * (1.f/MMENT);
        }
    }
    __syncthreads();
    if (tid == 0) {
        float sh = 1e-5f, st = 1e-5f;
        for (int m = 0; m < MMENT; m++) { sh += s_phatt[m]; st += s_ptatt[m]; }
        float ih = 1.f/sh, it = 1.f/st;
        for (int m = 0; m < MMENT; m++) { s_phatt[m] *= ih; s_ptatt[m] *= it; }
    }
    __syncthreads();
    for (int d = tid; d < DD; d += blockDim.x) {
        float nh = 0.f, nt = 0.f;
        #pragma unroll
        for (int m = 0; m < MMENT; m++) {
            nh += s_ptatt[m]*g_eemb[((size_t)(n*EE+h)*MMENT+m)*DD + d];
            nt += s_phatt[m]*g_eemb[((size_t)(n*EE+t)*MMENT+m)*DD + d];
        }
        g_hcat[(size_t)r*DIM3 + d] = nh;
        g_tcat[(size_t)r*DIM3 + d] = nt;
        g_q[(size_t)r*DIM2 + d]       = nh;
        g_q[(size_t)r*DIM2 + DD + d]  = nt;
    }
    float local = 0.f;
    for (int c = tid; c < CC; c += blockDim.x) {
        float na = 0.f, ta = 0.f;
        #pragma unroll
        for (int m = 0; m < MMENT; m++) {
            na += s_ptatt[m]*g_eatt[((size_t)(n*EE+h)*MMENT+m)*CC + c];
            ta += s_phatt[m]*g_eatt[((size_t)(n*EE+t)*MMENT+m)*CC + c];
        }
        float v = na*ta;
        g_pa[(size_t)r*CC + c] = v;
        local += v;
    }
    s_red[tid] = local;
    __syncthreads();
    for (int off = 128; off > 0; off >>= 1) {
        if (tid < off) s_red[tid] += s_red[tid+off];
        __syncthreads();
    }
    float inv = 1.f/(s_red[0] + 1e-5f);
    for (int c = tid; c < CC; c += blockDim.x)
        g_pa[(size_t)r*CC + c] *= inv;
}

// ---------------- SGEMM 128x128x8, f32x2 packed FMA, double-buffered ----------------
__global__ void __launch_bounds__(256) sgemm(
    int M, int Nn, int Kc, int S,
    const float* __restrict__ A, int lda, long long sA,
    const float* __restrict__ B, int ldb, long long sB,
    float* __restrict__ part, int Mtot)
{
    int b = blockIdx.z / S;
    int s = blockIdx.z % S;
    const float* Ab = A + (size_t)b*sA + (size_t)s*Kc;
    const float* Bb = B + (size_t)b*sB + (size_t)s*Kc*ldb;
    int m0 = blockIdx.y*128, n0 = blockIdx.x*128;
    __shared__ float As[2][8][256];   // A duplicated pairs: [k][2*row+{0,1}]
    __shared__ float Bs[2][8][128];
    int tid = threadIdx.x;
    int arow = tid >> 1, ak = (tid & 1)*4;
    int bk = tid >> 5,  bn = (tid & 31)*4;
    int tx = tid & 15,  ty = tid >> 4;

    unsigned long long acc[8][4];
    #pragma unroll
    for (int i = 0; i < 8; i++)
        #pragma unroll
        for (int j = 0; j < 4; j++) acc[i][j] = 0ull;

    // prologue prefetch (k0 = 0)
    float4 av = make_float4(0.f,0.f,0.f,0.f);
    if (m0 + arow < M)
        av = *(const float4*)(Ab + (size_t)(m0+arow)*lda + ak);
    float4 bv = *(const float4*)(Bb + (size_t)bk*ldb + n0 + bn);

    int nstage = Kc >> 3;
    for (int sidx = 0; sidx < nstage; sidx++) {
        int buf = sidx & 1;
        // store current tile (duplicated A)
        *(float2*)&As[buf][ak+0][2*arow] = make_float2(av.x, av.x);
        *(float2*)&As[buf][ak+1][2*arow] = make_float2(av.y, av.y);
        *(float2*)&As[buf][ak+2][2*arow] = make_float2(av.z, av.z);
        *(float2*)&As[buf][ak+3][2*arow] = make_float2(av.w, av.w);
        *(float4*)&Bs[buf][bk][bn] = bv;
        __syncthreads();
        // prefetch next tile into registers (overlaps compute)
        if (sidx + 1 < nstage) {
            int k0 = (sidx + 1) << 3;
            av = make_float4(0.f,0.f,0.f,0.f);
            if (m0 + arow < M)
                av = *(const float4*)(Ab + (size_t)(m0+arow)*lda + k0 + ak);
            bv = *(const float4*)(Bb + (size_t)(k0+bk)*ldb + n0 + bn);
        }
        // compute
        #pragma unroll
        for (int kk = 0; kk < 8; kk++) {
            const ulonglong2* ap = (const ulonglong2*)&As[buf][kk][ty*16];
            const ulonglong2* bp = (const ulonglong2*)&Bs[buf][kk][tx*8];
            ulonglong2 a0 = ap[0], a1 = ap[1], a2 = ap[2], a3 = ap[3];
            ulonglong2 b01 = bp[0], b23 = bp[1];
            unsigned long long aa[8] = {a0.x,a0.y,a1.x,a1.y,a2.x,a2.y,a3.x,a3.y};
            unsigned long long bb[4] = {b01.x,b01.y,b23.x,b23.y};
            #pragma unroll
            for (int i = 0; i < 8; i++)
                #pragma unroll
                for (int j = 0; j < 4; j++)
                    asm("fma.rn.f32x2 %0, %1, %2, %0;"
                        : "+l"(acc[i][j]) : "l"(aa[i]), "l"(bb[j]));
        }
        __syncthreads();
    }
    float* pbase = part + ((size_t)s*Mtot + (size_t)b*M)*Nn;
    #pragma unroll
    for (int i = 0; i < 8; i++) {
        int r = m0 + ty*8 + i;
        if (r < M) {
            float v[8];
            #pragma unroll
            for (int j = 0; j < 4; j++) {
                v[2*j]   = __uint_as_float((unsigned int)(acc[i][j] & 0xffffffffull));
                v[2*j+1] = __uint_as_float((unsigned int)(acc[i][j] >> 32));
            }
            float* prow = pbase + (size_t)r*Nn + n0 + tx*8;
            *(float4*)(prow)   = make_float4(v[0],v[1],v[2],v[3]);
            *(float4*)(prow+4) = make_float4(v[4],v[5],v[6],v[7]);
        }
    }
}

// ---------------- reduce partials + bias + relu + dual store ----------------
__global__ void reduce_ep(const float* __restrict__ part, int S, int Mtot, int Nn,
                          const float* __restrict__ bias, int dorelu,
                          float* __restrict__ dst1, int ld1,
                          float* __restrict__ dst2, int ld2)
{
    int idx = blockIdx.x*blockDim.x + threadIdx.x;
    if (idx >= Mtot*Nn) return;
    int r = idx / Nn, c = idx % Nn;
    float v = 0.f;
    for (int s = 0; s < S; s++)
        v += part[((size_t)s*Mtot + r)*Nn + c];
    if (bias) v += bias[c];
    if (dorelu) v = fmaxf(v, 0.f);
    dst1[(size_t)r*ld1 + c] = v;
    if (dst2) dst2[(size_t)r*ld2 + c] = v;
}

// ---------------- K7: score + masked softmax + path features ----------------
__global__ void k_scorepath(const int* __restrict__ hts, const float* __restrict__ battp)
{
    int r = blockIdx.x;
    int n = r / PP;
    int h = hts[r*2 + 0];
    int t = hts[r*2 + 1];
    __shared__ float s_q[DIM4];
    __shared__ float s_score[EE];
    __shared__ float s_aw[EE];
    int tid = threadIdx.x;
    for (int i = tid; i < DIM4; i += blockDim.x)
        s_q[i] = g_qW[(size_t)r*DIM4 + i];
    __syncthreads();
    int warp = tid >> 5, lane = tid & 31;
    float batt = battp[0];
    for (int v = warp; v < EE; v += 8) {
        const float* e1 = g_edge + ((size_t)((n*EE+h)*EE + v))*DD;
        const float* e2 = g_edge + ((size_t)((n*EE+v)*EE + t))*DD;
        const float* e3 = g_edge + ((size_t)((n*EE+t)*EE + v))*DD;
        const float* e4 = g_edge + ((size_t)((n*EE+v)*EE + h))*DD;
        float s = 0.f;
        for (int d = lane; d < DD; d += 32)
            s += s_q[d]*e1[d] + s_q[DD+d]*e2[d] + s_q[2*DD+d]*e3[d] + s_q[3*DD+d]*e4[d];
        #pragma unroll
        for (int off = 16; off; off >>= 1)
            s += __shfl_down_sync(0xffffffffu, s, off);
        if (lane == 0) s_score[v] = s + batt;
    }
    __syncthreads();
    if (tid == 0) {
        float mx = -1e38f;
        for (int v = 0; v < EE; v++) {
            float sc = (v == h || v == t) ? NEGV : s_score[v];
            s_score[v] = sc;
            mx = fmaxf(mx, sc);
        }
        float sum = 0.f;
        for (int v = 0; v < EE; v++) {
            float e = expf(s_score[v] - mx);
            s_aw[v] = e;
            sum += e;
        }
        float inv = 1.f/sum;
        for (int v = 0; v < EE; v++) s_aw[v] *= inv;
    }
    __syncthreads();
    for (int idx = tid; idx < DIM4; idx += blockDim.x) {
        int kk = idx / DD, d = idx % DD;
        const float* ep;
        size_t strideV;
        if (kk == 0)      { ep = g_edge + ((size_t)((n*EE+h)*EE))*DD + d;   strideV = DD; }
        else if (kk == 1) { ep = g_edge + ((size_t)(n*EE)*EE + t)*DD + d;   strideV = (size_t)EE*DD; }
        else if (kk == 2) { ep = g_edge + ((size_t)((n*EE+t)*EE))*DD + d;   strideV = DD; }
        else              { ep = g_edge + ((size_t)(n*EE)*EE + h)*DD + d;   strideV = (size_t)EE*DD; }
        float acc = 0.f;
        #pragma unroll 4
        for (int v = 0; v < EE; v++)
            acc += s_aw[v]*ep[(size_t)v*strideV];
        g_pathraw[(size_t)r*DIM4 + idx] = acc;
    }
}

// ---------------- K10: bilinear GEMM, f32x2 on row pairs ----------------
__global__ void __launch_bounds__(256) k_bil(const float* __restrict__ Wbil)
{
    __shared__ float ts_s[64][68];
    __shared__ float Ws[64*97];
    int r0 = blockIdx.x * 64;
    int k  = blockIdx.y;
    int tid = threadIdx.x;
    for (int idx = tid; idx < 64*64; idx += 256) {
        int rr = idx >> 6, j = idx & 63;
        int r = r0 + rr;
        ts_s[j][rr] = (r < NP) ? g_ts[(size_t)r*DD + k*64 + j] : 0.f;
    }
    int tx = tid & 15, ty = tid >> 4;
    int cols[7];
    #pragma unroll
    for (int ci = 0; ci < 7; ci++) {
        int c = ty + 16*ci;
        cols[ci] = (c < LL) ? c : 0;
    }
    unsigned long long accp[2][7];
    #pragma unroll
    for (int rp = 0; rp < 2; rp++)
        #pragma unroll
        for (int ci = 0; ci < 7; ci++) accp[rp][ci] = 0ull;
    for (int i = 0; i < 64; i++) {
        __syncthreads();
        for (int idx = tid; idx < 64*97; idx += 256)
            Ws[idx] = Wbil[(size_t)(k*4096 + i*64)*LL + idx];
        __syncthreads();
        unsigned long long acc2p[2][7];
        #pragma unroll
        for (int rp = 0; rp < 2; rp++)
            #pragma unroll
            for (int ci = 0; ci < 7; ci++) acc2p[rp][ci] = 0ull;
        #pragma unroll 4
        for (int j = 0; j < 64; j++) {
            ulonglong2 tv = *(const ulonglong2*)&ts_s[j][tx*4];
            #pragma unroll
            for (int ci = 0; ci < 7; ci++) {
                unsigned int wu = __float_as_uint(Ws[j*LL + cols[ci]]);
                unsigned long long wd;
                asm("mov.b64 %0, {%1, %1};" : "=l"(wd) : "r"(wu));
                asm("fma.rn.f32x2 %0, %1, %2, %0;" : "+l"(acc2p[0][ci]) : "l"(tv.x), "l"(wd));
                asm("fma.rn.f32x2 %0, %1, %2, %0;" : "+l"(acc2p[1][ci]) : "l"(tv.y), "l"(wd));
            }
        }
        // fold with hs column i
        float hv[4];
        #pragma unroll
        for (int ri = 0; ri < 4; ri++) {
            int r = r0 + tx*4 + ri;
            hv[ri] = (r < NP) ? g_hs[(size_t)r*DD + k*64 + i] : 0.f;
        }
        unsigned long long hp0, hp1;
        asm("mov.b64 %0, {%1, %2};" : "=l"(hp0) : "r"(__float_as_uint(hv[0])), "r"(__float_as_uint(hv[1])));
        asm("mov.b64 %0, {%1, %2};" : "=l"(hp1) : "r"(__float_as_uint(hv[2])), "r"(__float_as_uint(hv[3])));
        #pragma unroll
        for (int ci = 0; ci < 7; ci++) {
            asm("fma.rn.f32x2 %0, %1, %2, %0;" : "+l"(accp[0][ci]) : "l"(hp0), "l"(acc2p[0][ci]));
            asm("fma.rn.f32x2 %0, %1, %2, %0;" : "+l"(accp[1][ci]) : "l"(hp1), "l"(acc2p[1][ci]));
        }
    }
    #pragma unroll
    for (int rp = 0; rp < 2; rp++) {
        #pragma unroll
        for (int ri2 = 0; ri2 < 2; ri2++) {
            int r = r0 + tx*4 + rp*2 + ri2;
            if (r < NP) {
                #pragma unroll
                for (int ci = 0; ci < 7; ci++) {
                    int c = ty + 16*ci;
                    if (c < LL) {
                        unsigned long long u = accp[rp][ci];
                        float fv = ri2 ? __uint_as_float((unsigned int)(u >> 32))
                                       : __uint_as_float((unsigned int)(u & 0xffffffffull));
                        g_part[((size_t)k*NP + r)*LL + c] = fv;
                    }
                }
            }
        }
    }
}

__global__ void k_bilred(const float* __restrict__ bbil, float* __restrict__ out)
{
    int idx = blockIdx.x*blockDim.x + threadIdx.x;
    if (idx >= NP*LL) return;
    int r = idx / LL, l = idx % LL;
    float v = bbil[l];
    #pragma unroll
    for (int k = 0; k < 12; k++)
        v += g_part[((size_t)k*NP + r)*LL + l];
    out[idx] = v;
}

// ---------------- launcher ----------------
static float* symaddr(const void* sym)
{
    void* p = nullptr;
    cudaGetSymbolAddress(&p, sym);
    return (float*)p;
}

extern "C" void kernel_launch(void* const* d_in, const int* in_sizes, int n_in,
                              void* d_out, int out_size)
{
    const float* seq   = (const float*)d_in[0];
    const float* att   = (const float*)d_in[1];
    const int*   ms    = (const int*)  d_in[2];
    const int*   hts   = (const int*)  d_in[3];
    const float* Wm1   = (const float*)d_in[4];
    const float* Wm2   = (const float*)d_in[5];
    const float* bm    = (const float*)d_in[6];
    const float* Watt  = (const float*)d_in[7];
    const float* batt  = (const float*)d_in[8];
    const float* Wpath = (const float*)d_in[9];
    const float* bpath = (const float*)d_in[10];
    const float* Whead = (const float*)d_in[11];
    const float* bhead = (const float*)d_in[12];
    const float* Wtail = (const float*)d_in[13];
    const float* btail = (const float*)d_in[14];
    const float* Wbil  = (const float*)d_in[15];
    const float* bbil  = (const float*)d_in[16];
    float* out = (float*)d_out;

    float* glob   = symaddr(g_glob);
    float* gA     = symaddr(g_A);
    float* gB     = symaddr(g_B);
    float* q      = symaddr(g_q);
    float* pa     = symaddr(g_pa);
    float* hcat   = symaddr(g_hcat);
    float* tcat   = symaddr(g_tcat);
    float* qW     = symaddr(g_qW);
    float* praw   = symaddr(g_pathraw);
    float* hs     = symaddr(g_hs);
    float* ts     = symaddr(g_ts);
    float* part   = symaddr(g_part);

    // 1. gather
    k_gather<<<NN*EE, 256>>>(seq, att, ms);

    // 2. A = glob @ Wm1 ; B = glob @ Wm2   (M=80, N=768, K=768, split-K 12)
    sgemm<<<dim3(6,1,12), 256>>>(NN*EE, DD, 64, 12, glob, DD, 0, Wm1, DD, 0, part, NN*EE);
    reduce_ep<<<(NN*EE*DD+255)/256, 256>>>(part, 12, NN*EE, DD, nullptr, 0, gA, DD, nullptr, 0);
    sgemm<<<dim3(6,1,12), 256>>>(NN*EE, DD, 64, 12, glob, DD, 0, Wm2, DD, 0, part, NN*EE);
    reduce_ep<<<(NN*EE*DD+255)/256, 256>>>(part, 12, NN*EE, DD, nullptr, 0, gB, DD, nullptr, 0);

    // 3. edge
    k_edge<<<(NN*EE*EE*DD+255)/256, 256>>>(bm);

    // 4. pair attention -> q, hcat[:, :D], tcat[:, :D], pa
    k_pair<<<NP, 256>>>(hts, ms);

    // 5. rs = pa @ seq (batched per doc, split-K 4)
    sgemm<<<dim3(6,3,NN*4), 256>>>(PP, DD, CC/4, 4, pa, CC, (long long)PP*CC,
                                   seq, DD, (long long)CC*DD, part, NP);
    reduce_ep<<<(NP*DD+255)/256, 256>>>(part, 4, NP, DD, nullptr, 0,
                                        hcat + DD, DIM3, tcat + DD, DIM3);

    // 6. qW = q @ Watt  (1520 x 3072, K=1536)
    sgemm<<<dim3(24,12,1), 256>>>(NP, DIM4, DIM2, 1, q, DIM2, 0, Watt, DIM4, 0, part, NP);
    reduce_ep<<<(NP*DIM4+255)/256, 256>>>(part, 1, NP, DIM4, nullptr, 0, qW, DIM4, nullptr, 0);

    // 7. score/softmax/path features
    k_scorepath<<<NP, 256>>>(hts, batt);

    // 8. path = relu(pathraw @ Wpath + bpath)
    sgemm<<<dim3(6,12,4), 256>>>(NP, DD, DIM4/4, 4, praw, DIM4, 0, Wpath, DD, 0, part, NP);
    reduce_ep<<<(NP*DD+255)/256, 256>>>(part, 4, NP, DD, bpath, 1,
                                        hcat + 2*DD, DIM3, tcat + 2*DD, DIM3);

    // 9. hs / ts projections
    sgemm<<<dim3(6,12,4), 256>>>(NP, DD, DIM3/4, 4, hcat, DIM3, 0, Whead, DD, 0, part, NP);
    reduce_ep<<<(NP*DD+255)/256, 256>>>(part, 4, NP, DD, bhead, 1, hs, DD, nullptr, 0);
    sgemm<<<dim3(6,12,4), 256>>>(NP, DD, DIM3/4, 4, tcat, DIM3, 0, Wtail, DD, 0, part, NP);
    reduce_ep<<<(NP*DD+255)/256, 256>>>(part, 4, NP, DD, btail, 1, ts, DD, nullptr, 0);

    // 10. bilinear head
    k_bil<<<dim3((NP+63)/64, 12), 256>>>(Wbil);
    k_bilred<<<(NP*LL+255)/256, 256>>>(bbil, out);
}

// round 7
// speedup vs baseline: 2.1693x; 2.1693x over previous
#include <cuda_runtime.h>
#include <cstdint>
#include <math.h>

#define NN 4
#define CC 512
#define DD 768
#define HH 12
#define EE 20
#define MMENT 4
#define PP 380
#define NP 1520
#define LL 97
#define DIM2 1536
#define DIM3 2304
#define DIM4 3072
#define KBIL 49152
#define NEGV (-1e30f)

// ---------------- static device scratch ----------------
__device__ float g_eemb[NN*EE*MMENT*DD];
__device__ float g_eatt[NN*EE*MMENT*CC];
__device__ float g_glob[NN*EE*DD];
__device__ float g_A[NN*EE*DD];
__device__ float g_B[NN*EE*DD];
__device__ float g_edge[NN*EE*EE*DD];
__device__ float g_q[NP*DIM2];
__device__ float g_pa[NP*CC];
__device__ float g_hcat[NP*DIM3];
__device__ float g_tcat[NP*DIM3];
__device__ float g_qW[NP*DIM4];
__device__ float g_pathraw[NP*DIM4];
__device__ float g_hs[NP*DD];
__device__ float g_ts[NP*DD];
__device__ float g_part[4*NP*DD];
// transposed (K-major) weights for mma B operand
__device__ float g_wT_m1[DD*DD];
__device__ float g_wT_m2[DD*DD];
__device__ float g_wT_att[DIM4*DIM2];
__device__ float g_wT_path[DD*DIM4];
__device__ float g_wT_head[DD*DIM3];
__device__ float g_wT_tail[DD*DIM3];
__device__ float g_wT_bil[128*KBIL];   // rows 97..127 zero

// ---------------- helpers ----------------
__device__ __forceinline__ uint32_t f2tf32(float f) {
    uint32_t r;
    asm("cvt.rna.tf32.f32 %0, %1;" : "=r"(r) : "f"(f));
    return r;
}
__device__ __forceinline__ void mma_tf32(float* d, uint32_t a0, uint32_t a1,
                                         uint32_t a2, uint32_t a3,
                                         uint32_t b0, uint32_t b1)
{
    asm volatile(
        "mma.sync.aligned.m16n8k8.row.col.f32.tf32.tf32.f32 "
        "{%0,%1,%2,%3}, {%4,%5,%6,%7}, {%8,%9}, {%0,%1,%2,%3};"
        : "+f"(d[0]), "+f"(d[1]), "+f"(d[2]), "+f"(d[3])
        : "r"(a0), "r"(a1), "r"(a2), "r"(a3), "r"(b0), "r"(b1));
}

// gather one 128x32 A chunk + 128x32 B chunk into mma-fragment order (registers)
__device__ __forceinline__ void gatherAB(
    const float* __restrict__ A, int lda, int M, int m0,
    const float* __restrict__ BT, int ldbt, int n0,
    int k0, int tid, float (&av)[4][4], float (&bv)[8][2])
{
    #pragma unroll
    for (int t = 0; t < 4; t++) {
        int combo = tid + t*256;            // mt(3b) ks(2b) lane(5b)
        int mt = combo >> 7, ks = (combo >> 5) & 3, ln = combo & 31;
        int gg = ln >> 2, cc = ln & 3;
        int r0 = m0 + mt*16 + gg, r1 = r0 + 8;
        int c0 = k0 + ks*8 + cc;
        const float* Ar0 = A + (size_t)r0*lda + c0;
        const float* Ar1 = A + (size_t)r1*lda + c0;
        av[t][0] = (r0 < M) ? Ar0[0] : 0.f;
        av[t][1] = (r1 < M) ? Ar1[0] : 0.f;
        av[t][2] = (r0 < M) ? Ar0[4] : 0.f;
        av[t][3] = (r1 < M) ? Ar1[4] : 0.f;
    }
    #pragma unroll
    for (int t = 0; t < 8; t++) {
        int combo = tid + t*256;            // nt(4b) ks(2b) lane(5b)
        int nt = combo >> 7, ks = (combo >> 5) & 3, ln = combo & 31;
        int gg = ln >> 2, cc = ln & 3;
        int n = n0 + nt*8 + gg;
        const float* Br = BT + (size_t)n*ldbt + k0 + ks*8 + cc;
        bv[t][0] = Br[0];
        bv[t][1] = Br[4];
    }
}

__device__ __forceinline__ void storeAB(uint32_t* sA, uint32_t* sB, int tid,
                                        const float (&av)[4][4], const float (&bv)[8][2])
{
    #pragma unroll
    for (int t = 0; t < 4; t++) {
        int combo = tid + t*256;
        uint4 v = make_uint4(f2tf32(av[t][0]), f2tf32(av[t][1]),
                             f2tf32(av[t][2]), f2tf32(av[t][3]));
        *(uint4*)(sA + combo*4) = v;
    }
    #pragma unroll
    for (int t = 0; t < 8; t++) {
        int combo = tid + t*256;
        uint2 v = make_uint2(f2tf32(bv[t][0]), f2tf32(bv[t][1]));
        *(uint2*)(sB + combo*2) = v;
    }
}

__device__ __forceinline__ void computeChunk(const uint32_t* sA, const uint32_t* sB,
                                             int wm, int wn, int lane,
                                             float (&acc)[4][4][4])
{
    #pragma unroll
    for (int ks = 0; ks < 4; ks++) {
        uint32_t b[4][2];
        #pragma unroll
        for (int nt = 0; nt < 4; nt++) {
            uint2 bb = *(const uint2*)(sB + (((wn*4 + nt)*4 + ks)*32 + lane)*2);
            b[nt][0] = bb.x; b[nt][1] = bb.y;
        }
        #pragma unroll
        for (int mt = 0; mt < 4; mt++) {
            uint4 aa = *(const uint4*)(sA + (((wm*4 + mt)*4 + ks)*32 + lane)*4);
            #pragma unroll
            for (int nt = 0; nt < 4; nt++)
                mma_tf32(acc[mt][nt], aa.x, aa.y, aa.z, aa.w, b[nt][0], b[nt][1]);
        }
    }
}

// ================ tf32 warp-mma GEMM: dst = act(A[M,K] @ BT[N,K]^T + bias) ================
// grid: (N/128, ceil(M/128), S). If part!=null -> write split-K partials instead.
__global__ void __launch_bounds__(256) wgemm(
    int M, int nchunks, int S,
    const float* __restrict__ A, int lda,
    const float* __restrict__ BT, int ldbt,
    float* __restrict__ dst1, int ld1,
    const float* __restrict__ bias, int relu,
    float* __restrict__ dst2, int ld2,
    float* __restrict__ part, int Mtot, int Nn)
{
    extern __shared__ uint32_t sm[];
    uint32_t* sA = sm;            // 2 x 4096
    uint32_t* sB = sm + 8192;     // 2 x 4096
    int tid = threadIdx.x;
    int lane = tid & 31, wid = tid >> 5;
    int wm = wid >> 2, wn = wid & 3;
    int g = lane >> 2, c = lane & 3;
    int m0 = blockIdx.y*128, n0 = blockIdx.x*128;
    int z = blockIdx.z;
    int kbase = z*nchunks*32;

    float acc[4][4][4];
    #pragma unroll
    for (int i = 0; i < 4; i++)
        #pragma unroll
        for (int j = 0; j < 4; j++)
            #pragma unroll
            for (int k = 0; k < 4; k++) acc[i][j][k] = 0.f;

    float av[4][4]; float bv[8][2];
    gatherAB(A, lda, M, m0, BT, ldbt, n0, kbase, tid, av, bv);
    for (int kc = 0; kc < nchunks; kc++) {
        int buf = kc & 1;
        storeAB(sA + buf*4096, sB + buf*4096, tid, av, bv);
        __syncthreads();
        if (kc + 1 < nchunks)
            gatherAB(A, lda, M, m0, BT, ldbt, n0, kbase + (kc+1)*32, tid, av, bv);
        computeChunk(sA + buf*4096, sB + buf*4096, wm, wn, lane, acc);
    }

    #pragma unroll
    for (int mt = 0; mt < 4; mt++) {
        int r0 = m0 + wm*64 + mt*16 + g;
        int r1 = r0 + 8;
        #pragma unroll
        for (int nt = 0; nt < 4; nt++) {
            int c0 = n0 + wn*32 + nt*8 + 2*c;
            if (part) {
                float* p0 = part + ((size_t)z*Mtot + r0)*Nn + c0;
                float* p1 = part + ((size_t)z*Mtot + r1)*Nn + c0;
                if (r0 < M) { p0[0] = acc[mt][nt][0]; p0[1] = acc[mt][nt][1]; }
                if (r1 < M) { p1[0] = acc[mt][nt][2]; p1[1] = acc[mt][nt][3]; }
            } else {
                float b0 = bias ? bias[c0] : 0.f;
                float b1 = bias ? bias[c0+1] : 0.f;
                float v0 = acc[mt][nt][0] + b0, v1 = acc[mt][nt][1] + b1;
                float v2 = acc[mt][nt][2] + b0, v3 = acc[mt][nt][3] + b1;
                if (relu) { v0=fmaxf(v0,0.f); v1=fmaxf(v1,0.f); v2=fmaxf(v2,0.f); v3=fmaxf(v3,0.f); }
                if (r0 < M) {
                    dst1[(size_t)r0*ld1 + c0] = v0; dst1[(size_t)r0*ld1 + c0+1] = v1;
                    if (dst2) { dst2[(size_t)r0*ld2 + c0] = v0; dst2[(size_t)r0*ld2 + c0+1] = v1; }
                }
                if (r1 < M) {
                    dst1[(size_t)r1*ld1 + c0] = v2; dst1[(size_t)r1*ld1 + c0+1] = v3;
                    if (dst2) { dst2[(size_t)r1*ld2 + c0] = v2; dst2[(size_t)r1*ld2 + c0+1] = v3; }
                }
            }
        }
    }
}

// ===== bilinear: part[kb] = (hs_kb ⊗ ts_kb)[128-row tile] @ WbilT[kb], A built on the fly =====
__global__ void __launch_bounds__(256) wbil(const float* __restrict__ BT)
{
    extern __shared__ uint32_t sm[];
    uint32_t* sA = sm;             // 2 x 4096
    uint32_t* sB = sm + 8192;      // 2 x 4096
    float* hsf = (float*)(sm + 16384);          // [64][129]
    float* tsf = (float*)(sm + 16384 + 8256);   // [64][129]
    int tid = threadIdx.x;
    int lane = tid & 31, wid = tid >> 5;
    int wm = wid >> 2, wn = wid & 3;
    int g = lane >> 2, c = lane & 3;
    int m0 = blockIdx.x*128;
    int kb = blockIdx.y;

    for (int idx = tid; idx < 64*128; idx += 256) {
        int i = idx >> 7, r = idx & 127;
        int rg = m0 + r;
        hsf[i*129 + r] = (rg < NP) ? g_hs[(size_t)rg*DD + kb*64 + i] : 0.f;
        tsf[i*129 + r] = (rg < NP) ? g_ts[(size_t)rg*DD + kb*64 + i] : 0.f;
    }
    __syncthreads();

    float acc[4][4][4];
    #pragma unroll
    for (int i = 0; i < 4; i++)
        #pragma unroll
        for (int j = 0; j < 4; j++)
            #pragma unroll
            for (int k = 0; k < 4; k++) acc[i][j][k] = 0.f;

    float av[4][4]; float bv[8][2];
    const float* Bb = BT + (size_t)kb*4096;

    // gather chunk kc into av/bv
    auto gatherBil = [&](int kc) {
        int k0 = kc*32;
        #pragma unroll
        for (int t = 0; t < 4; t++) {
            int combo = tid + t*256;
            int mt = combo >> 7, ks = (combo >> 5) & 3, ln = combo & 31;
            int gg = ln >> 2, cc = ln & 3;
            int kl0 = k0 + ks*8 + cc;
            int ii = kl0 >> 6, j0 = kl0 & 63, j1 = (kl0 + 4) & 63;
            int r0 = mt*16 + gg, r1 = r0 + 8;
            float h0 = hsf[ii*129 + r0], h1 = hsf[ii*129 + r1];
            av[t][0] = h0 * tsf[j0*129 + r0];
            av[t][1] = h1 * tsf[j0*129 + r1];
            av[t][2] = h0 * tsf[j1*129 + r0];
            av[t][3] = h1 * tsf[j1*129 + r1];
        }
        #pragma unroll
        for (int t = 0; t < 8; t++) {
            int combo = tid + t*256;
            int nt = combo >> 7, ks = (combo >> 5) & 3, ln = combo & 31;
            int gg = ln >> 2, cc = ln & 3;
            int n = nt*8 + gg;
            const float* Br = Bb + (size_t)n*KBIL + k0 + ks*8 + cc;
            bv[t][0] = Br[0];
            bv[t][1] = Br[4];
        }
    };

    gatherBil(0);
    for (int kc = 0; kc < 128; kc++) {
        int buf = kc & 1;
        storeAB(sA + buf*4096, sB + buf*4096, tid, av, bv);
        __syncthreads();
        if (kc + 1 < 128) gatherBil(kc + 1);
        computeChunk(sA + buf*4096, sB + buf*4096, wm, wn, lane, acc);
    }

    #pragma unroll
    for (int mt = 0; mt < 4; mt++) {
        int r0 = m0 + wm*64 + mt*16 + g;
        int r1 = r0 + 8;
        #pragma unroll
        for (int nt = 0; nt < 4; nt++) {
            int c0 = wn*32 + nt*8 + 2*c;
            #pragma unroll
            for (int u = 0; u < 2; u++) {
                int col = c0 + u;
                if (col < LL) {
                    if (r0 < NP) g_part[((size_t)kb*NP + r0)*LL + col] = acc[mt][nt][u];
                    if (r1 < NP) g_part[((size_t)kb*NP + r1)*LL + col] = acc[mt][nt][2+u];
                }
            }
        }
    }
}

// ================= transpose: out[c][r] = in[r][c]; rows c in [C,Cout) -> 0 =================
__global__ void ktrans(const float* __restrict__ in, int R, int C, int Cout,
                       float* __restrict__ out)
{
    __shared__ float t[32][33];
    int c0 = blockIdx.x*32, r0 = blockIdx.y*32;
    int tx = threadIdx.x, ty = threadIdx.y;
    #pragma unroll
    for (int j = 0; j < 32; j += 8) {
        int r = r0 + ty + j, c = c0 + tx;
        t[ty+j][tx] = (r < R && c < C) ? in[(size_t)r*C + c] : 0.f;
    }
    __syncthreads();
    #pragma unroll
    for (int j = 0; j < 32; j += 8) {
        int c = c0 + ty + j, r = r0 + tx;
        if (c < Cout && r < R) out[(size_t)c*R + r] = t[tx][ty+j];
    }
}

// ---------------- K1: gather ----------------
__global__ void k_gather(const float* __restrict__ seq, const float* __restrict__ att,
                         const int* __restrict__ ms)
{
    int ne = blockIdx.x;
    int n  = ne / EE;
    int tid = threadIdx.x;
    for (int m = 0; m < MMENT; m++) {
        int pos = ms[ne*MMENT + m] + 1;
        const float* srow = seq + ((size_t)n*CC + pos)*DD;
        float* erow = g_eemb + ((size_t)ne*MMENT + m)*DD;
        for (int d = tid; d < DD; d += blockDim.x) erow[d] = srow[d];
        float* arow = g_eatt + ((size_t)ne*MMENT + m)*CC;
        for (int c = tid; c < CC; c += blockDim.x) {
            float s = 0.f;
            #pragma unroll
            for (int h = 0; h < HH; h++)
                s += att[(((size_t)n*HH + h)*CC + pos)*CC + c];
            arow[c] = s * (1.0f/HH);
        }
    }
    __syncthreads();
    for (int d = tid; d < DD; d += blockDim.x) {
        float x0 = g_eemb[((size_t)ne*MMENT+0)*DD+d];
        float x1 = g_eemb[((size_t)ne*MMENT+1)*DD+d];
        float x2 = g_eemb[((size_t)ne*MMENT+2)*DD+d];
        float x3 = g_eemb[((size_t)ne*MMENT+3)*DD+d];
        float mx = fmaxf(fmaxf(x0,x1), fmaxf(x2,x3));
        float s = expf(x0-mx)+expf(x1-mx)+expf(x2-mx)+expf(x3-mx);
        g_glob[(size_t)ne*DD + d] = mx + logf(s);
    }
}

// ---------------- K3: edge ----------------
__global__ void k_edge(const float* __restrict__ bm)
{
    int idx = blockIdx.x*blockDim.x + threadIdx.x;
    const int total = NN*EE*EE*DD;
    if (idx >= total) return;
    int d = idx % DD;
    int v = (idx / DD) % EE;
    int u = (idx / (DD*EE)) % EE;
    int n = idx / (DD*EE*EE);
    float val = g_A[((size_t)n*EE+u)*DD+d] + g_B[((size_t)n*EE+v)*DD+d] + bm[d];
    g_edge[idx] = fmaxf(val, 0.f);
}

// ---------------- K4: pair attention ----------------
__global__ void k_pair(const int* __restrict__ hts, const int* __restrict__ ms)
{
    int r = blockIdx.x;
    int n = r / PP;
    int h = hts[r*2 + 0];
    int t = hts[r*2 + 1];
    __shared__ int   s_ph[MMENT], s_pt[MMENT];
    __shared__ float s_phatt[MMENT], s_ptatt[MMENT];
    __shared__ float s_red[256];
    int tid = threadIdx.x;
    if (tid < MMENT) {
        s_ph[tid] = ms[((size_t)n*EE+h)*MMENT + tid] + 1;
        s_pt[tid] = ms[((size_t)n*EE+t)*MMENT + tid] + 1;
    }
    __syncthreads();
    if (tid < 2*MMENT) {
        int m2 = tid & (MMENT-1);
        float s = 0.f;
        if (tid < MMENT) {
            for (int m1 = 0; m1 < MMENT; m1++)
                s += g_eatt[((size_t)(n*EE+h)*MMENT+m1)*CC + s_pt[m2]];
            s_phatt[m2] = s * (1.f/MMENT);
        } else {
            for (int m1 = 0; m1 < MMENT; m1++)
                s += g_eatt[((size_t)(n*EE+t)*MMENT+m1)*CC + s_ph[m2]];
            s_ptatt[m2] = s * (1.f/MMENT);
        }
    }
    __syncthreads();
    if (tid == 0) {
        float sh = 1e-5f, st = 1e-5f;
        for (int m = 0; m < MMENT; m++) { sh += s_phatt[m]; st += s_ptatt[m]; }
        float ih = 1.f/sh, it = 1.f/st;
        for (int m = 0; m < MMENT; m++) { s_phatt[m] *= ih; s_ptatt[m] *= it; }
    }
    __syncthreads();
    for (int d = tid; d < DD; d += blockDim.x) {
        float nh = 0.f, nt = 0.f;
        #pragma unroll
        for (int m = 0; m < MMENT; m++) {
            nh += s_ptatt[m]*g_eemb[((size_t)(n*EE+h)*MMENT+m)*DD + d];
            nt += s_phatt[m]*g_eemb[((size_t)(n*EE+t)*MMENT+m)*DD + d];
        }
        g_hcat[(size_t)r*DIM3 + d] = nh;
        g_tcat[(size_t)r*DIM3 + d] = nt;
        g_q[(size_t)r*DIM2 + d]       = nh;
        g_q[(size_t)r*DIM2 + DD + d]  = nt;
    }
    float local = 0.f;
    for (int c = tid; c < CC; c += blockDim.x) {
        float na = 0.f, ta = 0.f;
        #pragma unroll
        for (int m = 0; m < MMENT; m++) {
            na += s_ptatt[m]*g_eatt[((size_t)(n*EE+h)*MMENT+m)*CC + c];
            ta += s_phatt[m]*g_eatt[((size_t)(n*EE+t)*MMENT+m)*CC + c];
        }
        float v = na*ta;
        g_pa[(size_t)r*CC + c] = v;
        local += v;
    }
    s_red[tid] = local;
    __syncthreads();
    for (int off = 128; off > 0; off >>= 1) {
        if (tid < off) s_red[tid] += s_red[tid+off];
        __syncthreads();
    }
    float inv = 1.f/(s_red[0] + 1e-5f);
    for (int c = tid; c < CC; c += blockDim.x)
        g_pa[(size_t)r*CC + c] *= inv;
}

// ---------------- fp32 SGEMM (rs only: batched per doc) ----------------
__global__ void __launch_bounds__(256) sgemm(
    int M, int Nn, int Kc, int S,
    const float* __restrict__ A, int lda, long long sA,
    const float* __restrict__ B, int ldb, long long sB,
    float* __restrict__ part, int Mtot)
{
    int b = blockIdx.z / S;
    int s = blockIdx.z % S;
    const float* Ab = A + (size_t)b*sA + (size_t)s*Kc;
    const float* Bb = B + (size_t)b*sB + (size_t)s*Kc*ldb;
    int m0 = blockIdx.y*128, n0 = blockIdx.x*128;
    __shared__ float As[8][128];
    __shared__ float Bs[8][128];
    int tid = threadIdx.x;
    int arow = tid >> 1, ak = (tid & 1)*4;
    int bk = tid >> 5,  bn = (tid & 31)*4;
    int tx = tid & 15,  ty = tid >> 4;
    float acc[8][8];
    #pragma unroll
    for (int i = 0; i < 8; i++)
        #pragma unroll
        for (int j = 0; j < 8; j++) acc[i][j] = 0.f;
    for (int k0 = 0; k0 < Kc; k0 += 8) {
        float4 av = make_float4(0.f,0.f,0.f,0.f);
        if (m0 + arow < M)
            av = *(const float4*)(Ab + (size_t)(m0+arow)*lda + k0 + ak);
        float4 bvv = *(const float4*)(Bb + (size_t)(k0+bk)*ldb + n0 + bn);
        __syncthreads();
        As[ak+0][arow] = av.x; As[ak+1][arow] = av.y;
        As[ak+2][arow] = av.z; As[ak+3][arow] = av.w;
        *(float4*)&Bs[bk][bn] = bvv;
        __syncthreads();
        #pragma unroll
        for (int kk = 0; kk < 8; kk++) {
            float a[8], bb[8];
            *(float4*)(a)    = *(const float4*)&As[kk][ty*8];
            *(float4*)(a+4)  = *(const float4*)&As[kk][ty*8+4];
            *(float4*)(bb)   = *(const float4*)&Bs[kk][tx*8];
            *(float4*)(bb+4) = *(const float4*)&Bs[kk][tx*8+4];
            #pragma unroll
            for (int i = 0; i < 8; i++)
                #pragma unroll
                for (int j = 0; j < 8; j++)
                    acc[i][j] += a[i]*bb[j];
        }
    }
    float* pbase = part + ((size_t)s*Mtot + (size_t)b*M)*Nn;
    #pragma unroll
    for (int i = 0; i < 8; i++) {
        int r = m0 + ty*8 + i;
        if (r < M) {
            float* prow = pbase + (size_t)r*Nn + n0 + tx*8;
            *(float4*)(prow)   = make_float4(acc[i][0],acc[i][1],acc[i][2],acc[i][3]);
            *(float4*)(prow+4) = make_float4(acc[i][4],acc[i][5],acc[i][6],acc[i][7]);
        }
    }
}

__global__ void reduce_ep(const float* __restrict__ part, int S, int Mtot, int Nn,
                          const float* __restrict__ bias, int dorelu,
                          float* __restrict__ dst1, int ld1,
                          float* __restrict__ dst2, int ld2)
{
    int idx = blockIdx.x*blockDim.x + threadIdx.x;
    if (idx >= Mtot*Nn) return;
    int r = idx / Nn, c = idx % Nn;
    float v = 0.f;
    for (int s = 0; s < S; s++)
        v += part[((size_t)s*Mtot + r)*Nn + c];
    if (bias) v += bias[c];
    if (dorelu) v = fmaxf(v, 0.f);
    dst1[(size_t)r*ld1 + c] = v;
    if (dst2) dst2[(size_t)r*ld2 + c] = v;
}

// ---------------- K7: score + masked softmax + path ----------------
__global__ void k_scorepath(const int* __restrict__ hts, const float* __restrict__ battp)
{
    int r = blockIdx.x;
    int n = r / PP;
    int h = hts[r*2 + 0];
    int t = hts[r*2 + 1];
    __shared__ float s_q[DIM4];
    __shared__ float s_score[EE];
    __shared__ float s_aw[EE];
    int tid = threadIdx.x;
    for (int i = tid; i < DIM4; i += blockDim.x)
        s_q[i] = g_qW[(size_t)r*DIM4 + i];
    __syncthreads();
    int warp = tid >> 5, lane = tid & 31;
    float batt = battp[0];
    for (int v = warp; v < EE; v += 8) {
        const float* e1 = g_edge + ((size_t)((n*EE+h)*EE + v))*DD;
        const float* e2 = g_edge + ((size_t)((n*EE+v)*EE + t))*DD;
        const float* e3 = g_edge + ((size_t)((n*EE+t)*EE + v))*DD;
        const float* e4 = g_edge + ((size_t)((n*EE+v)*EE + h))*DD;
        float s = 0.f;
        for (int d = lane; d < DD; d += 32)
            s += s_q[d]*e1[d] + s_q[DD+d]*e2[d] + s_q[2*DD+d]*e3[d] + s_q[3*DD+d]*e4[d];
        #pragma unroll
        for (int off = 16; off; off >>= 1)
            s += __shfl_down_sync(0xffffffffu, s, off);
        if (lane == 0) s_score[v] = s + batt;
    }
    __syncthreads();
    if (tid == 0) {
        float mx = -1e38f;
        for (int v = 0; v < EE; v++) {
            float sc = (v == h || v == t) ? NEGV : s_score[v];
            s_score[v] = sc;
            mx = fmaxf(mx, sc);
        }
        float sum = 0.f;
        for (int v = 0; v < EE; v++) {
            float e = expf(s_score[v] - mx);
            s_aw[v] = e;
            sum += e;
        }
        float inv = 1.f/sum;
        for (int v = 0; v < EE; v++) s_aw[v] *= inv;
    }
    __syncthreads();
    for (int idx = tid; idx < DIM4; idx += blockDim.x) {
        int kk = idx / DD, d = idx % DD;
        const float* ep;
        size_t strideV;
        if (kk == 0)      { ep = g_edge + ((size_t)((n*EE+h)*EE))*DD + d;   strideV = DD; }
        else if (kk == 1) { ep = g_edge + ((size_t)(n*EE)*EE + t)*DD + d;   strideV = (size_t)EE*DD; }
        else if (kk == 2) { ep = g_edge + ((size_t)((n*EE+t)*EE))*DD + d;   strideV = DD; }
        else              { ep = g_edge + ((size_t)(n*EE)*EE + h)*DD + d;   strideV = (size_t)EE*DD; }
        float acc = 0.f;
        #pragma unroll 4
        for (int v = 0; v < EE; v++)
            acc += s_aw[v]*ep[(size_t)v*strideV];
        g_pathraw[(size_t)r*DIM4 + idx] = acc;
    }
}

__global__ void k_bilred(const float* __restrict__ bbil, float* __restrict__ out)
{
    int idx = blockIdx.x*blockDim.x + threadIdx.x;
    if (idx >= NP*LL) return;
    int r = idx / LL, l = idx % LL;
    float v = bbil[l];
    #pragma unroll
    for (int k = 0; k < 12; k++)
        v += g_part[((size_t)k*NP + r)*LL + l];
    out[idx] = v;
}

// ---------------- launcher ----------------
static float* symaddr(const void* sym)
{
    void* p = nullptr;
    cudaGetSymbolAddress(&p, sym);
    return (float*)p;
}

extern "C" void kernel_launch(void* const* d_in, const int* in_sizes, int n_in,
                              void* d_out, int out_size)
{
    const float* seq   = (const float*)d_in[0];
    const float* att   = (const float*)d_in[1];
    const int*   ms    = (const int*)  d_in[2];
    const int*   hts   = (const int*)  d_in[3];
    const float* Wm1   = (const float*)d_in[4];
    const float* Wm2   = (const float*)d_in[5];
    const float* bm    = (const float*)d_in[6];
    const float* Watt  = (const float*)d_in[7];
    const float* batt  = (const float*)d_in[8];
    const float* Wpath = (const float*)d_in[9];
    const float* bpath = (const float*)d_in[10];
    const float* Whead = (const float*)d_in[11];
    const float* bhead = (const float*)d_in[12];
    const float* Wtail = (const float*)d_in[13];
    const float* btail = (const float*)d_in[14];
    const float* Wbil  = (const float*)d_in[15];
    const float* bbil  = (const float*)d_in[16];
    float* out = (float*)d_out;

    float* glob   = symaddr(g_glob);
    float* gA     = symaddr(g_A);
    float* gB     = symaddr(g_B);
    float* q      = symaddr(g_q);
    float* pa     = symaddr(g_pa);
    float* hcat   = symaddr(g_hcat);
    float* tcat   = symaddr(g_tcat);
    float* qW     = symaddr(g_qW);
    float* praw   = symaddr(g_pathraw);
    float* hs     = symaddr(g_hs);
    float* ts     = symaddr(g_ts);
    float* part   = symaddr(g_part);
    float* wTm1   = symaddr(g_wT_m1);
    float* wTm2   = symaddr(g_wT_m2);
    float* wTatt  = symaddr(g_wT_att);
    float* wTpath = symaddr(g_wT_path);
    float* wThead = symaddr(g_wT_head);
    float* wTtail = symaddr(g_wT_tail);
    float* wTbil  = symaddr(g_wT_bil);

    const int SMEM_WG = 65536;
    const int SMEM_WB = 65536 + 2*8256*4;
    cudaFuncSetAttribute(wgemm, cudaFuncAttributeMaxDynamicSharedMemorySize, SMEM_WG);
    cudaFuncSetAttribute(wbil,  cudaFuncAttributeMaxDynamicSharedMemorySize, SMEM_WB);

    // 0. weight transposes (K-major B operands)
    ktrans<<<dim3(DD/32,   DD/32),   dim3(32,8)>>>(Wm1,   DD,   DD,   DD,  wTm1);
    ktrans<<<dim3(DD/32,   DD/32),   dim3(32,8)>>>(Wm2,   DD,   DD,   DD,  wTm2);
    ktrans<<<dim3(DIM4/32, DIM2/32), dim3(32,8)>>>(Watt,  DIM2, DIM4, DIM4, wTatt);
    ktrans<<<dim3(DD/32,   DIM4/32), dim3(32,8)>>>(Wpath, DIM4, DD,   DD,   wTpath);
    ktrans<<<dim3(DD/32,   DIM3/32), dim3(32,8)>>>(Whead, DIM3, DD,   DD,   wThead);
    ktrans<<<dim3(DD/32,   DIM3/32), dim3(32,8)>>>(Wtail, DIM3, DD,   DD,   wTtail);
    ktrans<<<dim3(4, KBIL/32),       dim3(32,8)>>>(Wbil,  KBIL, LL,   128,  wTbil);

    // 1. gather
    k_gather<<<NN*EE, 256>>>(seq, att, ms);

    // 2. A = glob @ Wm1 ; B = glob @ Wm2  (tf32 mma, split-K 4)
    wgemm<<<dim3(6,1,4), 256, SMEM_WG>>>(NN*EE, 6, 4, glob, DD, wTm1, DD,
                                         nullptr, 0, nullptr, 0, nullptr, 0,
                                         part, NN*EE, DD);
    reduce_ep<<<(NN*EE*DD+255)/256, 256>>>(part, 4, NN*EE, DD, nullptr, 0, gA, DD, nullptr, 0);
    wgemm<<<dim3(6,1,4), 256, SMEM_WG>>>(NN*EE, 6, 4, glob, DD, wTm2, DD,
                                         nullptr, 0, nullptr, 0, nullptr, 0,
                                         part, NN*EE, DD);
    reduce_ep<<<(NN*EE*DD+255)/256, 256>>>(part, 4, NN*EE, DD, nullptr, 0, gB, DD, nullptr, 0);

    // 3. edge
    k_edge<<<(NN*EE*EE*DD+255)/256, 256>>>(bm);

    // 4. pair attention
    k_pair<<<NP, 256>>>(hts, ms);

    // 5. rs = pa @ seq (fp32, batched, split-K 4)
    sgemm<<<dim3(6,3,NN*4), 256>>>(PP, DD, CC/4, 4, pa, CC, (long long)PP*CC,
                                   seq, DD, (long long)CC*DD, part, NP);
    reduce_ep<<<(NP*DD+255)/256, 256>>>(part, 4, NP, DD, nullptr, 0,
                                        hcat + DD, DIM3, tcat + DD, DIM3);

    // 6. qW = q @ Watt  (tf32 mma, direct epilogue)
    wgemm<<<dim3(24,12,1), 256, SMEM_WG>>>(NP, 48, 1, q, DIM2, wTatt, DIM2,
                                           qW, DIM4, nullptr, 0, nullptr, 0,
                                           nullptr, 0, 0);

    // 7. score/softmax/path
    k_scorepath<<<NP, 256>>>(hts, batt);

    // 8. path = relu(pathraw @ Wpath + bpath)  (tf32 mma, split-K 2)
    wgemm<<<dim3(6,12,2), 256, SMEM_WG>>>(NP, 48, 2, praw, DIM4, wTpath, DIM4,
                                          nullptr, 0, nullptr, 0, nullptr, 0,
                                          part, NP, DD);
    reduce_ep<<<(NP*DD+255)/256, 256>>>(part, 2, NP, DD, bpath, 1,
                                        hcat + 2*DD, DIM3, tcat + 2*DD, DIM3);

    // 9. hs / ts projections (tf32 mma, split-K 2)
    wgemm<<<dim3(6,12,2), 256, SMEM_WG>>>(NP, 36, 2, hcat, DIM3, wThead, DIM3,
                                          nullptr, 0, nullptr, 0, nullptr, 0,
                                          part, NP, DD);
    reduce_ep<<<(NP*DD+255)/256, 256>>>(part, 2, NP, DD, bhead, 1, hs, DD, nullptr, 0);
    wgemm<<<dim3(6,12,2), 256, SMEM_WG>>>(NP, 36, 2, tcat, DIM3, wTtail, DIM3,
                                          nullptr, 0, nullptr, 0, nullptr, 0,
                                          part, NP, DD);
    reduce_ep<<<(NP*DD+255)/256, 256>>>(part, 2, NP, DD, btail, 1, ts, DD, nullptr, 0);

    // 10. bilinear head (tf32 mma, fused outer-product A)
    wbil<<<dim3(12,12), 256, SMEM_WB>>>(wTbil);
    k_bilred<<<(NP*LL+255)/256, 256>>>(bbil, out);
}